// round 13
// baseline (speedup 1.0000x reference)
#include <cuda_runtime.h>
#include <cstdint>

// Chamfer loss, symmetric single pass, FULLY FUSED single kernel (period-1
// launch sequence so ncu -s 5 -c 1 must capture it).
// Phase 1: 268M unique pair distances -> rowmin partials (16 slices) +
//          colmin partials (8 slices), same mainloop as R10 (best variant).
// Grid sync: arrival counter + spin (all 256 CTAs co-resident: 34.4KB smem,
//            ~80 regs -> >=3 CTAs/SM on 148 SMs).
// Phase 2: each thread reduces one row query (min of 16) + one col query
//          (min of 8); block sum -> atomicAdd; last CTA finalizes + resets.

#define BATCH 16
#define NPTS  4096
#define CSTR  6
#define THREADS 256
#define NW    8
#define I8    512
#define JH    2048
#define GRID  (BATCH * 8 * 2)     // 256 CTAs

#define NQ    (BATCH * NPTS)      // 65536 per side

__device__ float        g_rowpart[16 * NQ];   // [slice=jh*8+w][b*4096+i]
__device__ float        g_colpart[8 * NQ];    // [slice=i8][b*4096+j]
__device__ float        g_acc;                // zero-init; reset each launch
__device__ unsigned int g_count1;             // phase-1 arrivals
__device__ unsigned int g_count2;             // phase-2 arrivals

typedef unsigned long long ull;

__device__ __forceinline__ ull pk2(float lo, float hi) {
    ull r; asm("mov.b64 %0, {%1, %2};" : "=l"(r) : "f"(lo), "f"(hi)); return r;
}
__device__ __forceinline__ ull fma2(ull a, ull b, ull c) {
    ull d; asm("fma.rn.f32x2 %0, %1, %2, %3;" : "=l"(d) : "l"(a), "l"(b), "l"(c)); return d;
}
__device__ __forceinline__ ull add2(ull a, ull b) {
    ull d; asm("add.rn.f32x2 %0, %1, %2;" : "=l"(d) : "l"(a), "l"(b)); return d;
}
__device__ __forceinline__ void upk2(ull v, float& lo, float& hi) {
    asm("mov.b64 {%0, %1}, %2;" : "=f"(lo), "=f"(hi) : "l"(v));
}
__device__ __forceinline__ float4 vmin4(float4 a, float4 b) {
    return make_float4(fminf(a.x, b.x), fminf(a.y, b.y),
                       fminf(a.z, b.z), fminf(a.w, b.w));
}

__global__ void __launch_bounds__(THREADS)
k_fused(const float* __restrict__ x, const float* __restrict__ y,
        float* __restrict__ out) {
    __shared__ ulonglong2 sx[I8][2];        // 16 KB
    __shared__ float      buf[NW][16][36];  // 18.4 KB
    __shared__ float      ws[NW];

    const int bid = blockIdx.x;
    const int jh  = bid & 1;
    const int i8  = (bid >> 1) & 7;
    const int b   = bid >> 4;

    const float* xb = x + (size_t)b * NPTS * CSTR;
    const float* yb = y + (size_t)b * NPTS * CSTR;

    const int tid  = threadIdx.x;
    const int w    = tid >> 5;
    const int lane = tid & 31;

    // ---- Phase 1: pair sweep ----
    const int ibase = i8 * I8;
    for (int t = tid; t < I8; t += THREADS) {
        const float* p = xb + (size_t)(ibase + t) * CSTR;
        float a = p[0], c = p[1], e = p[2];
        float rx = fmaf(a, a, fmaf(c, c, e * e));
        ulonglong2 v0, v1;
        v0.x = pk2(a, a);  v0.y = pk2(c, c);
        v1.x = pk2(e, e);  v1.y = pk2(rx, rx);
        sx[t][0] = v0;  sx[t][1] = v1;
    }

    ull ax[4], ay[4], az[4], ryp[4];
    const int j0 = jh * JH + w * 256 + lane * 8;
#pragma unroll
    for (int p = 0; p < 4; p++) {
        const float* pj = yb + (size_t)(j0 + 2 * p) * CSTR;
        float a0 = pj[0], b0 = pj[1], c0 = pj[2];
        float a1 = pj[6], b1 = pj[7], c1 = pj[8];
        float rr0 = fmaf(a0, a0, fmaf(b0, b0, c0 * c0));
        float rr1 = fmaf(a1, a1, fmaf(b1, b1, c1 * c1));
        ax[p]  = pk2(-2.0f * a0, -2.0f * a1);
        ay[p]  = pk2(-2.0f * b0, -2.0f * b1);
        az[p]  = pk2(-2.0f * c0, -2.0f * c1);
        ryp[p] = pk2(rr0, rr1);
    }

    float cm[8];
#pragma unroll
    for (int k = 0; k < 8; k++) cm[k] = 3.4e38f;

    __syncthreads();

    float* rowp = g_rowpart + (size_t)(jh * 8 + w) * NQ + b * NPTS + ibase;

    for (int blk = 0; blk < I8 / 16; blk++) {
#pragma unroll 4
        for (int s = 0; s < 16; s++) {
            const int i = blk * 16 + s;
            ulonglong2 v0 = sx[i][0];
            ulonglong2 v1 = sx[i][1];
            float e0, e1, e2, e3, e4, e5, e6, e7;
            upk2(add2(fma2(v0.x, ax[0], fma2(v0.y, ay[0], fma2(v1.x, az[0], ryp[0]))), v1.y), e0, e1);
            upk2(add2(fma2(v0.x, ax[1], fma2(v0.y, ay[1], fma2(v1.x, az[1], ryp[1]))), v1.y), e2, e3);
            upk2(add2(fma2(v0.x, ax[2], fma2(v0.y, ay[2], fma2(v1.x, az[2], ryp[2]))), v1.y), e4, e5);
            upk2(add2(fma2(v0.x, ax[3], fma2(v0.y, ay[3], fma2(v1.x, az[3], ryp[3]))), v1.y), e6, e7);

            cm[0] = fminf(cm[0], e0); cm[1] = fminf(cm[1], e1);
            cm[2] = fminf(cm[2], e2); cm[3] = fminf(cm[3], e3);
            cm[4] = fminf(cm[4], e4); cm[5] = fminf(cm[5], e5);
            cm[6] = fminf(cm[6], e6); cm[7] = fminf(cm[7], e7);

            float t = fminf(fminf(fminf(e0, e1), fminf(e2, e3)),
                            fminf(fminf(e4, e5), fminf(e6, e7)));
            buf[w][s][lane] = t;
        }
        __syncwarp();
        {
            const int r = lane & 15, h = lane >> 4;
            const float* rowv = &buf[w][r][h * 16];
            float4 a0 = *(const float4*)(rowv + 0);
            float4 a1 = *(const float4*)(rowv + 4);
            float4 a2 = *(const float4*)(rowv + 8);
            float4 a3 = *(const float4*)(rowv + 12);
            float m = fminf(fminf(fminf(a0.x, a0.y), fminf(a0.z, a0.w)),
                            fminf(fminf(a1.x, a1.y), fminf(a1.z, a1.w)));
            m = fminf(m, fminf(fminf(fminf(a2.x, a2.y), fminf(a2.z, a2.w)),
                               fminf(fminf(a3.x, a3.y), fminf(a3.z, a3.w))));
            m = fminf(m, __shfl_xor_sync(0xffffffffu, m, 16));
            if (h == 0) rowp[blk * 16 + r] = m;
        }
        __syncwarp();
    }

    float* colp = g_colpart + (size_t)i8 * NQ + b * NPTS + j0;
    *(float4*)(colp + 0) = make_float4(cm[0], cm[1], cm[2], cm[3]);
    *(float4*)(colp + 4) = make_float4(cm[4], cm[5], cm[6], cm[7]);

    // ---- Grid-wide sync (all CTAs co-resident) ----
    __threadfence();
    __syncthreads();
    if (tid == 0) {
        atomicAdd(&g_count1, 1u);
        while (*(volatile unsigned int*)&g_count1 < GRID) __nanosleep(64);
    }
    __syncthreads();
    __threadfence();

    // ---- Phase 2: distributed reduce. thread handles 1 row + 1 col query.
    float s;
    {
        const int g = bid * THREADS + tid;     // 0..65535
        float m0 = g_rowpart[g];
#pragma unroll
        for (int sl = 1; sl < 16; sl++)
            m0 = fminf(m0, g_rowpart[(size_t)sl * NQ + g]);
        float m1 = g_colpart[g];
#pragma unroll
        for (int sl = 1; sl < 8; sl++)
            m1 = fminf(m1, g_colpart[(size_t)sl * NQ + g]);
        s = m0 + m1;
    }

#pragma unroll
    for (int o = 16; o > 0; o >>= 1)
        s += __shfl_xor_sync(0xffffffffu, s, o);
    if (lane == 0) ws[w] = s;
    __syncthreads();

    if (tid == 0) {
        float t = 0.0f;
#pragma unroll
        for (int u = 0; u < NW; u++) t += ws[u];
        atomicAdd(&g_acc, t);
        __threadfence();
        unsigned int arrived = atomicAdd(&g_count2, 1u);
        if (arrived == GRID - 1) {
            __threadfence();
            float total = *((volatile float*)&g_acc);
            out[0] = total * (1.0f / (float)NQ);
            g_acc    = 0.0f;      // restore invariants for next graph replay
            g_count1 = 0u;
            g_count2 = 0u;
        }
    }
}

extern "C" void kernel_launch(void* const* d_in, const int* in_sizes, int n_in,
                              void* d_out, int out_size) {
    const float* x = (const float*)d_in[0];
    const float* y = (const float*)d_in[1];
    float* out = (float*)d_out;
    (void)in_sizes; (void)n_in; (void)out_size;

    k_fused<<<GRID, THREADS>>>(x, y, out);
}

// round 15
// speedup vs baseline: 1.1304x; 1.1304x over previous
#include <cuda_runtime.h>
#include <cstdint>

// Chamfer loss, symmetric single pass, fused single kernel.
// R15 = R13 + 3-input min (min.f32 d,a,b,c -> FMNMX3, sm_90+) and 2-i-step
// processing: row tree 7->4 ops, colmin 8->4 ops per i-step.

#define BATCH 16
#define NPTS  4096
#define CSTR  6
#define THREADS 256
#define NW    8
#define I8    512
#define JH    2048
#define GRID  (BATCH * 8 * 2)     // 256 CTAs

#define NQ    (BATCH * NPTS)      // 65536 per side

__device__ float        g_rowpart[16 * NQ];   // [slice=jh*8+w][b*4096+i]
__device__ float        g_colpart[8 * NQ];    // [slice=i8][b*4096+j]
__device__ float        g_acc;
__device__ unsigned int g_count1;
__device__ unsigned int g_count2;

typedef unsigned long long ull;

__device__ __forceinline__ ull pk2(float lo, float hi) {
    ull r; asm("mov.b64 %0, {%1, %2};" : "=l"(r) : "f"(lo), "f"(hi)); return r;
}
__device__ __forceinline__ ull fma2(ull a, ull b, ull c) {
    ull d; asm("fma.rn.f32x2 %0, %1, %2, %3;" : "=l"(d) : "l"(a), "l"(b), "l"(c)); return d;
}
__device__ __forceinline__ ull add2(ull a, ull b) {
    ull d; asm("add.rn.f32x2 %0, %1, %2;" : "=l"(d) : "l"(a), "l"(b)); return d;
}
__device__ __forceinline__ void upk2(ull v, float& lo, float& hi) {
    asm("mov.b64 {%0, %1}, %2;" : "=f"(lo), "=f"(hi) : "l"(v));
}
__device__ __forceinline__ float min3f(float a, float b, float c) {
    float d; asm("min.f32 %0, %1, %2, %3;" : "=f"(d) : "f"(a), "f"(b), "f"(c)); return d;
}

__global__ void __launch_bounds__(THREADS)
k_fused(const float* __restrict__ x, const float* __restrict__ y,
        float* __restrict__ out) {
    __shared__ ulonglong2 sx[I8][2];        // 16 KB
    __shared__ float      buf[NW][16][36];  // 18.4 KB
    __shared__ float      ws[NW];

    const int bid = blockIdx.x;
    const int jh  = bid & 1;
    const int i8  = (bid >> 1) & 7;
    const int b   = bid >> 4;

    const float* xb = x + (size_t)b * NPTS * CSTR;
    const float* yb = y + (size_t)b * NPTS * CSTR;

    const int tid  = threadIdx.x;
    const int w    = tid >> 5;
    const int lane = tid & 31;

    // ---- Phase 1: pair sweep ----
    const int ibase = i8 * I8;
    for (int t = tid; t < I8; t += THREADS) {
        const float* p = xb + (size_t)(ibase + t) * CSTR;
        float a = p[0], c = p[1], e = p[2];
        float rx = fmaf(a, a, fmaf(c, c, e * e));
        ulonglong2 v0, v1;
        v0.x = pk2(a, a);  v0.y = pk2(c, c);
        v1.x = pk2(e, e);  v1.y = pk2(rx, rx);
        sx[t][0] = v0;  sx[t][1] = v1;
    }

    ull ax[4], ay[4], az[4], ryp[4];
    const int j0 = jh * JH + w * 256 + lane * 8;
#pragma unroll
    for (int p = 0; p < 4; p++) {
        const float* pj = yb + (size_t)(j0 + 2 * p) * CSTR;
        float a0 = pj[0], b0 = pj[1], c0 = pj[2];
        float a1 = pj[6], b1 = pj[7], c1 = pj[8];
        float rr0 = fmaf(a0, a0, fmaf(b0, b0, c0 * c0));
        float rr1 = fmaf(a1, a1, fmaf(b1, b1, c1 * c1));
        ax[p]  = pk2(-2.0f * a0, -2.0f * a1);
        ay[p]  = pk2(-2.0f * b0, -2.0f * b1);
        az[p]  = pk2(-2.0f * c0, -2.0f * c1);
        ryp[p] = pk2(rr0, rr1);
    }

    float cm[8];
#pragma unroll
    for (int k = 0; k < 8; k++) cm[k] = 3.4e38f;

    __syncthreads();

    float* rowp = g_rowpart + (size_t)(jh * 8 + w) * NQ + b * NPTS + ibase;

    for (int blk = 0; blk < I8 / 16; blk++) {
#pragma unroll 4
        for (int s = 0; s < 16; s += 2) {
            const int i = blk * 16 + s;
            // ---- i0 ----
            ulonglong2 u0 = sx[i][0];
            ulonglong2 u1 = sx[i][1];
            float e0, e1, e2, e3, e4, e5, e6, e7;
            upk2(add2(fma2(u0.x, ax[0], fma2(u0.y, ay[0], fma2(u1.x, az[0], ryp[0]))), u1.y), e0, e1);
            upk2(add2(fma2(u0.x, ax[1], fma2(u0.y, ay[1], fma2(u1.x, az[1], ryp[1]))), u1.y), e2, e3);
            upk2(add2(fma2(u0.x, ax[2], fma2(u0.y, ay[2], fma2(u1.x, az[2], ryp[2]))), u1.y), e4, e5);
            upk2(add2(fma2(u0.x, ax[3], fma2(u0.y, ay[3], fma2(u1.x, az[3], ryp[3]))), u1.y), e6, e7);
            // ---- i1 ----
            ulonglong2 t0 = sx[i + 1][0];
            ulonglong2 t1 = sx[i + 1][1];
            float f0, f1, f2, f3, f4, f5, f6, f7;
            upk2(add2(fma2(t0.x, ax[0], fma2(t0.y, ay[0], fma2(t1.x, az[0], ryp[0]))), t1.y), f0, f1);
            upk2(add2(fma2(t0.x, ax[1], fma2(t0.y, ay[1], fma2(t1.x, az[1], ryp[1]))), t1.y), f2, f3);
            upk2(add2(fma2(t0.x, ax[2], fma2(t0.y, ay[2], fma2(t1.x, az[2], ryp[2]))), t1.y), f4, f5);
            upk2(add2(fma2(t0.x, ax[3], fma2(t0.y, ay[3], fma2(t1.x, az[3], ryp[3]))), t1.y), f6, f7);

            // row trees (4 ops each via min3)
            {
                float m1 = min3f(e0, e1, e2);
                float m2 = min3f(e3, e4, e5);
                float m3 = min3f(e6, e7, m1);
                buf[w][s][lane] = fminf(m2, m3);
            }
            {
                float m1 = min3f(f0, f1, f2);
                float m2 = min3f(f3, f4, f5);
                float m3 = min3f(f6, f7, m1);
                buf[w][s + 1][lane] = fminf(m2, m3);
            }

            // colmin across both i's (8 min3 per 2 i-steps)
            cm[0] = min3f(cm[0], e0, f0);
            cm[1] = min3f(cm[1], e1, f1);
            cm[2] = min3f(cm[2], e2, f2);
            cm[3] = min3f(cm[3], e3, f3);
            cm[4] = min3f(cm[4], e4, f4);
            cm[5] = min3f(cm[5], e5, f5);
            cm[6] = min3f(cm[6], e6, f6);
            cm[7] = min3f(cm[7], e7, f7);
        }
        __syncwarp();
        {
            const int r = lane & 15, h = lane >> 4;
            const float* rowv = &buf[w][r][h * 16];
            float4 a0 = *(const float4*)(rowv + 0);
            float4 a1 = *(const float4*)(rowv + 4);
            float4 a2 = *(const float4*)(rowv + 8);
            float4 a3 = *(const float4*)(rowv + 12);
            float m = min3f(min3f(a0.x, a0.y, a0.z),
                            min3f(a0.w, a1.x, a1.y),
                            min3f(a1.z, a1.w, a2.x));
            m = min3f(m, min3f(a2.y, a2.z, a2.w),
                         min3f(a3.x, a3.y, fminf(a3.z, a3.w)));
            m = fminf(m, __shfl_xor_sync(0xffffffffu, m, 16));
            if (h == 0) rowp[blk * 16 + r] = m;
        }
        __syncwarp();
    }

    float* colp = g_colpart + (size_t)i8 * NQ + b * NPTS + j0;
    *(float4*)(colp + 0) = make_float4(cm[0], cm[1], cm[2], cm[3]);
    *(float4*)(colp + 4) = make_float4(cm[4], cm[5], cm[6], cm[7]);

    // ---- Grid-wide sync ----
    __threadfence();
    __syncthreads();
    if (tid == 0) {
        atomicAdd(&g_count1, 1u);
        while (*(volatile unsigned int*)&g_count1 < GRID) __nanosleep(64);
    }
    __syncthreads();
    __threadfence();

    // ---- Phase 2: distributed reduce ----
    float s;
    {
        const int g = bid * THREADS + tid;
        float m0 = g_rowpart[g];
#pragma unroll
        for (int sl = 1; sl < 16; sl++)
            m0 = fminf(m0, g_rowpart[(size_t)sl * NQ + g]);
        float m1 = g_colpart[g];
#pragma unroll
        for (int sl = 1; sl < 8; sl++)
            m1 = fminf(m1, g_colpart[(size_t)sl * NQ + g]);
        s = m0 + m1;
    }

#pragma unroll
    for (int o = 16; o > 0; o >>= 1)
        s += __shfl_xor_sync(0xffffffffu, s, o);
    if (lane == 0) ws[w] = s;
    __syncthreads();

    if (tid == 0) {
        float t = 0.0f;
#pragma unroll
        for (int u = 0; u < NW; u++) t += ws[u];
        atomicAdd(&g_acc, t);
        __threadfence();
        unsigned int arrived = atomicAdd(&g_count2, 1u);
        if (arrived == GRID - 1) {
            __threadfence();
            float total = *((volatile float*)&g_acc);
            out[0] = total * (1.0f / (float)NQ);
            g_acc    = 0.0f;
            g_count1 = 0u;
            g_count2 = 0u;
        }
    }
}

extern "C" void kernel_launch(void* const* d_in, const int* in_sizes, int n_in,
                              void* d_out, int out_size) {
    const float* x = (const float*)d_in[0];
    const float* y = (const float*)d_in[1];
    float* out = (float*)d_out;
    (void)in_sizes; (void)n_in; (void)out_size;

    k_fused<<<GRID, THREADS>>>(x, y, out);
}